// round 1
// baseline (speedup 1.0000x reference)
#include <cuda_runtime.h>

#define HIDDEN 1024
#define HEADS  16
#define DKH    64
#define BB     2
#define NN     2048
#define ROWS   (BB*NN)   // 4096

// Scratch: projected Q/K/V and attention context (each 16 MB, static device mem)
__device__ float g_Q[ROWS * HIDDEN];
__device__ float g_K[ROWS * HIDDEN];
__device__ float g_V[ROWS * HIDDEN];
__device__ float g_C[ROWS * HIDDEN];

// ---------------------------------------------------------------------------
// Generic SGEMM: C[M,N] = A[M,K] @ W[K,N] + bias[N]
// BM=BN=128, BK=16, 256 threads, 8x8 microtile (split 64+64 layout).
// Assumes M%128==0, N%128==0, K%16==0 (true here: 4096/1024/1024).
// ---------------------------------------------------------------------------
__global__ void __launch_bounds__(256) gemm_bias_kernel(
    const float* __restrict__ A, const float* __restrict__ W,
    const float* __restrict__ bias, float* __restrict__ C,
    int M, int N, int K)
{
    __shared__ float As[16][132];   // A tile transposed [k][m], padded
    __shared__ float Bs[16][128];   // W tile [k][n]

    const int tid  = threadIdx.x;
    const int trow = tid >> 4;      // 0..15
    const int tcol = tid & 15;      // 0..15
    const int bm = blockIdx.y;
    const int bn = blockIdx.x;

    const float* Ablk = A + (size_t)bm * 128 * K;
    const float* Wblk = W + (size_t)bn * 128;

    float acc[8][8];
#pragma unroll
    for (int i = 0; i < 8; i++)
#pragma unroll
        for (int j = 0; j < 8; j++) acc[i][j] = 0.f;

    for (int k0 = 0; k0 < K; k0 += 16) {
        // Load A tile 128x16, store transposed
#pragma unroll
        for (int ld = 0; ld < 2; ld++) {
            int li  = tid + ld * 256;         // 0..511
            int row = li >> 2;                // 0..127
            int c4  = li & 3;                 // 0..3
            float4 v = *(const float4*)(Ablk + (size_t)row * K + k0 + c4 * 4);
            As[c4 * 4 + 0][row] = v.x;
            As[c4 * 4 + 1][row] = v.y;
            As[c4 * 4 + 2][row] = v.z;
            As[c4 * 4 + 3][row] = v.w;
        }
        // Load W tile 16x128
#pragma unroll
        for (int ld = 0; ld < 2; ld++) {
            int li  = tid + ld * 256;
            int row = li >> 5;                // 0..15
            int c4  = li & 31;                // 0..31
            *(float4*)&Bs[row][c4 * 4] =
                *(const float4*)(Wblk + (size_t)(k0 + row) * N + c4 * 4);
        }
        __syncthreads();

#pragma unroll
        for (int kk = 0; kk < 16; kk++) {
            float a[8], b[8];
            *(float4*)&a[0] = *(const float4*)&As[kk][trow * 4];
            *(float4*)&a[4] = *(const float4*)&As[kk][64 + trow * 4];
            *(float4*)&b[0] = *(const float4*)&Bs[kk][tcol * 4];
            *(float4*)&b[4] = *(const float4*)&Bs[kk][64 + tcol * 4];
#pragma unroll
            for (int i = 0; i < 8; i++)
#pragma unroll
                for (int j = 0; j < 8; j++)
                    acc[i][j] += a[i] * b[j];
        }
        __syncthreads();
    }

    // Epilogue: rows {trow*4+i, 64+trow*4+i}, cols {tcol*4+j, 64+tcol*4+j}
    const int colbase = bn * 128;
#pragma unroll
    for (int i = 0; i < 8; i++) {
        int row = bm * 128 + ((i < 4) ? (trow * 4 + i) : (64 + trow * 4 + (i - 4)));
#pragma unroll
        for (int jh = 0; jh < 2; jh++) {
            int col = colbase + jh * 64 + tcol * 4;
            float4 bv = *(const float4*)(bias + col);
            float4 o;
            o.x = acc[i][jh * 4 + 0] + bv.x;
            o.y = acc[i][jh * 4 + 1] + bv.y;
            o.z = acc[i][jh * 4 + 2] + bv.z;
            o.w = acc[i][jh * 4 + 3] + bv.w;
            *(float4*)(C + (size_t)row * N + col) = o;
        }
    }
}

// ---------------------------------------------------------------------------
// Flash attention (fp32, online softmax). One block = 64 query rows of one
// (b, h). Br=Bc=64, Dk=64. 256 threads: thread (ty,tx) ty=tid/16, tx=tid%16
// owns rows {4ty..4ty+3} and cols/dims {tx, 16+tx, 32+tx, 48+tx}.
// smem (dynamic): Qs,Ks,Vs,Ps each [64][68] fp32  => 69632 B
// ---------------------------------------------------------------------------
#define FPAD 68
#define FSM_BYTES (4 * 64 * FPAD * 4)

__global__ void __launch_bounds__(256) flash_kernel(
    const float* __restrict__ bias, const float* __restrict__ mask,
    float* __restrict__ ctx)
{
    extern __shared__ float sm[];
    float* Qs = sm;                    // [64][68]
    float* Ks = sm + 64 * FPAD;
    float* Vs = sm + 2 * 64 * FPAD;
    float* Ps = sm + 3 * 64 * FPAD;

    const int tid = threadIdx.x;
    const int ty  = tid >> 4;    // 0..15
    const int tx  = tid & 15;    // 0..15
    const int qb  = blockIdx.x;  // 0..31
    const int h   = blockIdx.y;
    const int b   = blockIdx.z;
    const int q0  = qb * 64;
    const float scale = 0.125f;  // 1/sqrt(64)

    const float* Qg = g_Q + (size_t)b * NN * HIDDEN + h * DKH;
    const float* Kg = g_K + (size_t)b * NN * HIDDEN + h * DKH;
    const float* Vg = g_V + (size_t)b * NN * HIDDEN + h * DKH;

    // Load Q tile (64 rows x 64 dims)
#pragma unroll
    for (int ld = 0; ld < 4; ld++) {
        int li = tid + ld * 256;     // 0..1023
        int r  = li >> 4;            // 0..63
        int d4 = li & 15;            // 0..15
        *(float4*)&Qs[r * FPAD + d4 * 4] =
            *(const float4*)(Qg + (size_t)(q0 + r) * HIDDEN + d4 * 4);
    }

    float O[4][4];
    float mrun[4], lsum[4];
#pragma unroll
    for (int i = 0; i < 4; i++) {
        mrun[i] = -1e30f; lsum[i] = 0.f;
#pragma unroll
        for (int j = 0; j < 4; j++) O[i][j] = 0.f;
    }

    const float* biasBase = bias + ((size_t)b * NN + q0) * NN;
    const float* maskBase = mask + ((size_t)b * NN + q0) * NN;

    for (int kt = 0; kt < NN / 64; kt++) {
        const int k0 = kt * 64;
        __syncthreads();   // protect Ks/Vs/Ps from previous iteration's readers

        // Load K, V tiles
#pragma unroll
        for (int ld = 0; ld < 4; ld++) {
            int li = tid + ld * 256;
            int r  = li >> 4;
            int d4 = li & 15;
            *(float4*)&Ks[r * FPAD + d4 * 4] =
                *(const float4*)(Kg + (size_t)(k0 + r) * HIDDEN + d4 * 4);
            *(float4*)&Vs[r * FPAD + d4 * 4] =
                *(const float4*)(Vg + (size_t)(k0 + r) * HIDDEN + d4 * 4);
        }
        __syncthreads();

        // Phase A: S[4r][4c] = Q·K^T
        float acc[4][4];
#pragma unroll
        for (int ri = 0; ri < 4; ri++)
#pragma unroll
            for (int ci = 0; ci < 4; ci++) acc[ri][ci] = 0.f;

#pragma unroll 4
        for (int kc = 0; kc < 16; kc++) {
            float4 kv[4];
#pragma unroll
            for (int ci = 0; ci < 4; ci++)
                kv[ci] = *(const float4*)&Ks[(ci * 16 + tx) * FPAD + kc * 4];
#pragma unroll
            for (int ri = 0; ri < 4; ri++) {
                float4 qv = *(const float4*)&Qs[(ty * 4 + ri) * FPAD + kc * 4];
#pragma unroll
                for (int ci = 0; ci < 4; ci++) {
                    acc[ri][ci] += qv.x * kv[ci].x;
                    acc[ri][ci] += qv.y * kv[ci].y;
                    acc[ri][ci] += qv.z * kv[ci].z;
                    acc[ri][ci] += qv.w * kv[ci].w;
                }
            }
        }

        // scale + bias + mask, then online softmax per row
#pragma unroll
        for (int ri = 0; ri < 4; ri++) {
            const int lrow = ty * 4 + ri;
            const float* bR = biasBase + (size_t)lrow * NN + k0;
            const float* mR = maskBase + (size_t)lrow * NN + k0;
#pragma unroll
            for (int ci = 0; ci < 4; ci++) {
                int c = ci * 16 + tx;
                acc[ri][ci] = acc[ri][ci] * scale + __ldg(bR + c) + __ldg(mR + c);
            }
            // row max across 4 regs + 16 lanes
            float mx = fmaxf(fmaxf(acc[ri][0], acc[ri][1]),
                             fmaxf(acc[ri][2], acc[ri][3]));
            mx = fmaxf(mx, __shfl_xor_sync(0xffffffffu, mx, 1));
            mx = fmaxf(mx, __shfl_xor_sync(0xffffffffu, mx, 2));
            mx = fmaxf(mx, __shfl_xor_sync(0xffffffffu, mx, 4));
            mx = fmaxf(mx, __shfl_xor_sync(0xffffffffu, mx, 8));

            float mnew = fmaxf(mrun[ri], mx);
            float corr = __expf(mrun[ri] - mnew);
            float rs = 0.f;
#pragma unroll
            for (int ci = 0; ci < 4; ci++) {
                float p = __expf(acc[ri][ci] - mnew);
                Ps[lrow * FPAD + ci * 16 + tx] = p;
                rs += p;
            }
            rs += __shfl_xor_sync(0xffffffffu, rs, 1);
            rs += __shfl_xor_sync(0xffffffffu, rs, 2);
            rs += __shfl_xor_sync(0xffffffffu, rs, 4);
            rs += __shfl_xor_sync(0xffffffffu, rs, 8);

            lsum[ri] = lsum[ri] * corr + rs;
            mrun[ri] = mnew;
#pragma unroll
            for (int di = 0; di < 4; di++) O[ri][di] *= corr;
        }
        __syncthreads();   // Ps visible to all

        // Phase B: O += P @ V
#pragma unroll 8
        for (int c = 0; c < 64; c++) {
            float p[4], vv[4];
#pragma unroll
            for (int ri = 0; ri < 4; ri++)
                p[ri] = Ps[(ty * 4 + ri) * FPAD + c];
#pragma unroll
            for (int di = 0; di < 4; di++)
                vv[di] = Vs[c * FPAD + di * 16 + tx];
#pragma unroll
            for (int ri = 0; ri < 4; ri++)
#pragma unroll
                for (int di = 0; di < 4; di++)
                    O[ri][di] += p[ri] * vv[di];
        }
    }

    // Epilogue: ctx[b, q0+row, h*64+d] = O / l
#pragma unroll
    for (int ri = 0; ri < 4; ri++) {
        int grow = q0 + ty * 4 + ri;
        float invl = 1.f / lsum[ri];
#pragma unroll
        for (int di = 0; di < 4; di++) {
            int d = di * 16 + tx;
            ctx[((size_t)b * NN + grow) * HIDDEN + h * DKH + d] = O[ri][di] * invl;
        }
    }
}

// ---------------------------------------------------------------------------
extern "C" void kernel_launch(void* const* d_in, const int* in_sizes, int n_in,
                              void* d_out, int out_size)
{
    const float* q    = (const float*)d_in[0];
    const float* k    = (const float*)d_in[1];
    const float* v    = (const float*)d_in[2];
    const float* abia = (const float*)d_in[3];
    const float* amask= (const float*)d_in[4];
    const float* Wq   = (const float*)d_in[5];
    const float* bq   = (const float*)d_in[6];
    const float* Wk   = (const float*)d_in[7];
    const float* bk   = (const float*)d_in[8];
    const float* Wv   = (const float*)d_in[9];
    const float* bv   = (const float*)d_in[10];
    const float* Wo   = (const float*)d_in[11];
    const float* bo   = (const float*)d_in[12];
    float* out = (float*)d_out;

    float *Qp, *Kp, *Vp, *Cp;
    cudaGetSymbolAddress((void**)&Qp, g_Q);
    cudaGetSymbolAddress((void**)&Kp, g_K);
    cudaGetSymbolAddress((void**)&Vp, g_V);
    cudaGetSymbolAddress((void**)&Cp, g_C);

    cudaFuncSetAttribute(flash_kernel,
                         cudaFuncAttributeMaxDynamicSharedMemorySize, FSM_BYTES);

    dim3 gb(HIDDEN / 128, ROWS / 128);   // (8, 32)
    gemm_bias_kernel<<<gb, 256>>>(q, Wq, bq, Qp, ROWS, HIDDEN, HIDDEN);
    gemm_bias_kernel<<<gb, 256>>>(k, Wk, bk, Kp, ROWS, HIDDEN, HIDDEN);
    gemm_bias_kernel<<<gb, 256>>>(v, Wv, bv, Vp, ROWS, HIDDEN, HIDDEN);

    dim3 gf(NN / 64, HEADS, BB);         // (32, 16, 2)
    flash_kernel<<<gf, 256, FSM_BYTES>>>(abia, amask, Cp);

    gemm_bias_kernel<<<gb, 256>>>(Cp, Wo, bo, out, ROWS, HIDDEN, HIDDEN);
}